// round 3
// baseline (speedup 1.0000x reference)
#include <cuda_runtime.h>
#include <cuda_bf16.h>

// Problem constants
#define BB   32
#define NEX  1024
#define NKC  128
#define DH   64

// ---------------- scratch (device globals; no allocations allowed) ----------
__device__ float g_x[BB * 64];            // x = x_id @ W_ex.T        (32,64)
__device__ float g_kci[BB * NKC];         // ex @ ex_graph            (32,128)
__device__ float g_kcg[NKC * NKC];        // sigmoid(kc_gamma)        (128,128)
__device__ float g_epart[NKC * 64];       // e @ W_e.T + fpart_b      (128,64)
__device__ float g_git[BB * 192];         // x @ tgru_wih.T + bih     (32,192)
__device__ float g_newh[BB * NKC * 64];   // new_h                    (4096,64)
__device__ float g_dpart[BB * NKC * 64];  // delta_h @ W_dh.T         (4096,64)
// transposed weights: [k][t] layout so inner-loop loads are lane-coalesced
__device__ float g_twihT[64 * 192];
__device__ float g_twhhT[64 * 192];
__device__ float g_WdhT[64 * 64];
__device__ float g_ulinT[64 * 64];
__device__ float g_uwihT[64 * 192];
__device__ float g_uwhhT[64 * 192];

__device__ __forceinline__ float sigf(float v)      { return 1.f / (1.f + __expf(-v)); }
__device__ __forceinline__ float tanhfast(float v)  { return 2.f / (1.f + __expf(-2.f * v)) - 1.f; }

// ---------------- K0: all independent precompute --------------------------
// blocks 0..63   : x (warp-per-output, 4 outputs/warp)
// blocks 64..71  : kcg = sigmoid(kc_gamma)
// block  72      : epart
// blocks 73..88  : weight transposes (flat index over 57344 elems)
// blocks 89..104 : kci (2 batches per block)
__global__ void k0(const float* __restrict__ ex, const float* __restrict__ su,
                   const float* __restrict__ ex_graph, const float* __restrict__ kc_gamma,
                   const float* __restrict__ W_ex, const float* __restrict__ W_kc,
                   const float* __restrict__ tgru_wih, const float* __restrict__ tgru_whh,
                   const float* __restrict__ fpart_w, const float* __restrict__ fpart_b,
                   const float* __restrict__ ulin_w,
                   const float* __restrict__ ugru_wih, const float* __restrict__ ugru_whh)
{
    int blk = blockIdx.x, tid = threadIdx.x;

    if (blk < 64) {
        // x[b,e] = su*dot(ex[b], W_ex[e,0:1024]) + (1-su)*dot(ex[b], W_ex[e,1024:2048])
        int warp = blk * 8 + (tid >> 5);
        int lane = tid & 31;
        #pragma unroll
        for (int q = 0; q < 4; q++) {
            int oid = warp * 4 + q;            // 0..2047
            int b = oid >> 6, e = oid & 63;
            const float* wrow = W_ex + e * 2048;
            const float* exr  = ex + b * 1024;
            float a1 = 0.f, a2 = 0.f;
            for (int n = lane; n < 1024; n += 32) {
                float ev = exr[n];
                a1 = fmaf(ev, wrow[n],        a1);
                a2 = fmaf(ev, wrow[1024 + n], a2);
            }
            #pragma unroll
            for (int o = 16; o; o >>= 1) {
                a1 += __shfl_xor_sync(0xffffffffu, a1, o);
                a2 += __shfl_xor_sync(0xffffffffu, a2, o);
            }
            if (lane == 0) {
                float s = su[b];
                g_x[oid] = s * a1 + (1.f - s) * a2;
            }
        }
    } else if (blk < 72) {
        int base = (blk - 64) * 2048;
        for (int i = tid; i < 2048; i += 256)
            g_kcg[base + i] = sigf(kc_gamma[base + i]);
    } else if (blk == 72) {
        // epart[j][d] = fpart_b[d] + sum_k W_kc[k,j] * fpart_w[d, 64+k]
        __shared__ float we_s[64][65];   // padded: conflict-free lane-varying-d reads
        for (int i = tid; i < 64 * 64; i += 256) {
            int dd = i >> 6, k = i & 63;
            we_s[dd][k] = fpart_w[dd * 128 + 64 + k];
        }
        __syncthreads();
        for (int i = tid; i < NKC * 64; i += 256) {
            int j = i >> 6, d = i & 63;
            float acc = fpart_b[d];
            #pragma unroll 8
            for (int k = 0; k < 64; k++)
                acc = fmaf(W_kc[k * 128 + j], we_s[d][k], acc);
            g_epart[i] = acc;
        }
    } else if (blk < 89) {
        int idx0 = (blk - 73) * 3584;
        for (int c = 0; c < 3584; c += 256) {
            int idx = idx0 + c + tid;
            if (idx < 12288)      { int k = idx / 192, t = idx % 192; g_twihT[idx] = tgru_wih[t * 64 + k]; }
            else if (idx < 24576) { int r = idx - 12288; int k = r / 192, t = r % 192; g_twhhT[r] = tgru_whh[t * 64 + k]; }
            else if (idx < 36864) { int r = idx - 24576; int k = r / 192, t = r % 192; g_uwihT[r] = ugru_wih[t * 64 + k]; }
            else if (idx < 49152) { int r = idx - 36864; int k = r / 192, t = r % 192; g_uwhhT[r] = ugru_whh[t * 64 + k]; }
            else if (idx < 53248) { int r = idx - 49152; int k = r >> 6, d = r & 63;  g_WdhT[r]  = fpart_w[d * 128 + k]; }
            else                  { int r = idx - 53248; int k = r >> 6, d = r & 63;  g_ulinT[r] = ulin_w[d * 64 + k]; }
        }
    } else {
        // kci[b,j] = sum_n ex[b,n] * ex_graph[n,j]   (lanes over j -> coalesced)
        int bb = (blk - 89) * 2;
        __shared__ float ex_s[2][1024];
        for (int i = tid; i < 2048; i += 256)
            ex_s[i >> 10][i & 1023] = ex[bb * 1024 + i];
        __syncthreads();
        int j = tid & 127, bh = tid >> 7;
        float acc = 0.f;
        #pragma unroll 4
        for (int n = 0; n < 1024; n++)
            acc = fmaf(ex_s[bh][n], ex_graph[n * 128 + j], acc);
        g_kci[(bb + bh) * 128 + j] = acc;
    }
}

// ---------------- K1: gi_t = x @ tgru_wih.T + bih (per batch) --------------
__global__ void k1(const float* __restrict__ tgru_bih)
{
    int b = blockIdx.x, t = threadIdx.x;   // 192 threads
    __shared__ float x_s[64];
    if (t < 64) x_s[t] = g_x[b * 64 + t];
    __syncthreads();
    float acc = tgru_bih[t];
    #pragma unroll 8
    for (int k = 0; k < 64; k++)
        acc = fmaf(x_s[k], g_twihT[k * 192 + t], acc);
    g_git[b * 192 + t] = acc;
}

// ---------------- K2: th-GRU + new_h + dpart (4 rows / 256-thread block) ---
__global__ void k2(const float* __restrict__ h, const float* __restrict__ tgru_bhh)
{
    __shared__ float h_s[4][64];
    __shared__ float delta_s[4][64];
    int tid = threadIdx.x;
    int l = tid >> 6, d = tid & 63;
    int row = blockIdx.x * 4 + l;          // 0..4095
    int b = row >> 7;
    float hv = h[row * 64 + d];
    h_s[l][d] = hv;
    float kciv = g_kci[row];
    float gir = g_git[b * 192 + d];
    float giz = g_git[b * 192 + 64 + d];
    float gin = g_git[b * 192 + 128 + d];
    __syncthreads();
    float ar = tgru_bhh[d], az = tgru_bhh[64 + d], an = tgru_bhh[128 + d];
    #pragma unroll 8
    for (int k = 0; k < 64; k++) {
        float hk = h_s[l][k];                       // LDS broadcast (warp has one l)
        ar = fmaf(hk, g_twhhT[k * 192 + d],       ar);
        az = fmaf(hk, g_twhhT[k * 192 + 64 + d],  az);
        an = fmaf(hk, g_twhhT[k * 192 + 128 + d], an);
    }
    float r = sigf(gir + ar);
    float z = sigf(giz + az);
    float n = tanhfast(gin + r * an);
    float th = (1.f - z) * n + z * hv;
    float delta = kciv * (th - hv);
    float nh = hv + delta;
    g_newh[row * 64 + d] = nh;
    delta_s[l][d] = delta;
    __syncthreads();
    float acc = 0.f;
    #pragma unroll 8
    for (int k = 0; k < 64; k++)
        acc = fmaf(delta_s[l][k], g_WdhT[k * 64 + d], acc);
    g_dpart[row * 64 + d] = acc;
}

// ---------------- K3: partj reduce + ulin + u-GRU + output ------------------
// grid (8 jtiles, 32 b), 1024 threads = (jl 0..15) x (d 0..63)
// smem: phase1 = dpart[128][64] (32KB) + kcgw[128][16] (8KB); phase2 aliases.
__global__ void __launch_bounds__(1024) k3(
    const float* __restrict__ ugru_bih, const float* __restrict__ ugru_bhh,
    const float* __restrict__ ulin_b, float* __restrict__ out)
{
    __shared__ float sraw[10240];  // 40KB
    float (*dpart_s)[64] = (float(*)[64])sraw;            // [128][64]
    float (*kcgw_s)[16]  = (float(*)[16])(sraw + 8192);   // [128][16]
    // phase-2 aliases (valid only after the barrier that ends phase 1)
    float (*partj_s)[64] = (float(*)[64])sraw;            // [16][64]
    float (*outj_s)[64]  = (float(*)[64])(sraw + 1024);   // [16][64]
    float (*newh_s)[64]  = (float(*)[64])(sraw + 2048);   // [16][64]

    int jt = blockIdx.x, b = blockIdx.y;
    int tid = threadIdx.x;
    int jl = tid >> 6, d = tid & 63;
    int j = jt * 16 + jl;

    const float* dp = g_dpart + b * (NKC * 64);
    for (int i = tid; i < NKC * 64; i += 1024)
        dpart_s[0][i] = dp[i];
    for (int i = tid; i < NKC * 16; i += 1024) {
        int ii = i >> 4, jj = i & 15;
        kcgw_s[ii][jj] = g_kcg[ii * 128 + jt * 16 + jj] * g_kci[b * 128 + ii];
    }
    float ep = g_epart[j * 64 + d];
    __syncthreads();

    // partj[b,j,d] = sum_i relu(dpart[i][d] + epart[j][d]) * kcgw[i][jl]
    // kcj[b,j]     = sum_i kcgw[i][jl]  (free)
    float acc = 0.f, wk = 0.f;
    #pragma unroll 4
    for (int i = 0; i < NKC; i++) {
        float wv  = kcgw_s[i][jl];                 // broadcast within warp
        float pre = dpart_s[i][d] + ep;            // conflict-free
        acc = fmaf(fmaxf(pre, 0.f), wv, acc);
        wk += wv;
    }
    __syncthreads();     // phase 1 smem now dead; safe to alias

    partj_s[jl][d] = acc;
    newh_s[jl][d]  = g_newh[(b * 128 + j) * 64 + d];
    __syncthreads();

    // outj = relu(partj @ ulin_w.T + ulin_b)
    float o = ulin_b[d];
    #pragma unroll 8
    for (int k = 0; k < 64; k++)
        o = fmaf(partj_s[jl][k], g_ulinT[k * 64 + d], o);
    o = fmaxf(o, 0.f);
    outj_s[jl][d] = o;
    __syncthreads();

    // u-GRU: gi = outj @ ugru_wih.T + bih ; gh = new_h @ ugru_whh.T + bhh
    float gr = ugru_bih[d], gz = ugru_bih[64 + d], gn = ugru_bih[128 + d];
    float hr = ugru_bhh[d], hz = ugru_bhh[64 + d], hn = ugru_bhh[128 + d];
    #pragma unroll 4
    for (int k = 0; k < 64; k++) {
        float ok = outj_s[jl][k];
        float nk = newh_s[jl][k];
        gr = fmaf(ok, g_uwihT[k * 192 + d],       gr);
        gz = fmaf(ok, g_uwihT[k * 192 + 64 + d],  gz);
        gn = fmaf(ok, g_uwihT[k * 192 + 128 + d], gn);
        hr = fmaf(nk, g_uwhhT[k * 192 + d],       hr);
        hz = fmaf(nk, g_uwhhT[k * 192 + 64 + d],  hz);
        hn = fmaf(nk, g_uwhhT[k * 192 + 128 + d], hn);
    }
    float r = sigf(gr + hr);
    float z = sigf(gz + hz);
    float n = tanhfast(gn + r * hn);
    float nh = newh_s[jl][d];
    float uh = (1.f - z) * n + z * nh;
    // h_out = (1-kcj)*new_h + kcj*uh
    out[(b * 128 + j) * 64 + d] = nh + wk * (uh - nh);
}

// ---------------- launch ----------------------------------------------------
extern "C" void kernel_launch(void* const* d_in, const int* in_sizes, int n_in,
                              void* d_out, int out_size)
{
    const float* h        = (const float*)d_in[0];
    const float* ex       = (const float*)d_in[1];
    const float* su       = (const float*)d_in[2];
    const float* ex_graph = (const float*)d_in[3];
    const float* kc_gamma = (const float*)d_in[4];
    const float* W_ex     = (const float*)d_in[5];
    const float* W_kc     = (const float*)d_in[6];
    const float* tgru_wih = (const float*)d_in[7];
    const float* tgru_whh = (const float*)d_in[8];
    const float* tgru_bih = (const float*)d_in[9];
    const float* tgru_bhh = (const float*)d_in[10];
    const float* fpart_w  = (const float*)d_in[11];
    const float* fpart_b  = (const float*)d_in[12];
    const float* ulin_w   = (const float*)d_in[13];
    const float* ulin_b   = (const float*)d_in[14];
    const float* ugru_wih = (const float*)d_in[15];
    const float* ugru_whh = (const float*)d_in[16];
    const float* ugru_bih = (const float*)d_in[17];
    const float* ugru_bhh = (const float*)d_in[18];
    float* out = (float*)d_out;

    k0<<<105, 256>>>(ex, su, ex_graph, kc_gamma, W_ex, W_kc,
                     tgru_wih, tgru_whh, fpart_w, fpart_b, ulin_w,
                     ugru_wih, ugru_whh);
    k1<<<32, 192>>>(tgru_bih);
    k2<<<1024, 256>>>(h, tgru_bhh);
    dim3 g3(8, 32);
    k3<<<g3, 1024>>>(ugru_bih, ugru_bhh, ulin_b, out);
}